// round 1
// baseline (speedup 1.0000x reference)
#include <cuda_runtime.h>

// ---------------- problem constants ----------------
static constexpr int NNODE = 10000;
static constexpr int NEDGE = 50000;
static constexpr int NSC   = 48;    // NS
static constexpr int NVC   = 10;    // NV
static constexpr int HID   = 128;
static constexpr int WTOT  = 3364;  // 2304 + 480 + 100 + 480
static constexpr int OFF2  = 2304;
static constexpr int OFF3  = 2784;
static constexpr int OFF4  = 2884;
static constexpr int TB    = 128;                      // edges per tile
static constexpr int NBLK  = (NEDGE + TB - 1) / TB;    // 391

#define EPS_BN     1e-5f
#define INV_SQRT3  0.57735026918962576f
#define NORM01     0.13130643285972254f   /* 1/sqrt(58) */

// ---------------- scratch (static device memory; no cudaMalloc) ----------------
__device__ float g_hT[(size_t)HID * NEDGE];   // h transposed [k][e], 25.6 MB
__device__ float g_sum[(size_t)NNODE * 78];   // per-node message sums
__device__ float g_cnt[NNODE];                // per-node edge counts
__device__ float g_stats[106];                // [0:48) sum_s, [48:96) sumsq_s, [96:106) sum v^2

// ---------------- K0: zero scratch ----------------
__global__ void k_zero() {
  int idx = blockIdx.x * blockDim.x + threadIdx.x;
  int stride = gridDim.x * blockDim.x;
  for (int i = idx; i < NNODE * 78; i += stride) g_sum[i] = 0.f;
  for (int i = idx; i < NNODE; i += stride) g_cnt[i] = 0.f;
  if (idx < 106) g_stats[idx] = 0.f;
}

// ---------------- K1: h = relu(edge_attr @ W1 + b1), stored transposed ----------------
static constexpr int K1_SMEM = (128 * 132 + 128 * 128) * 4;

__global__ __launch_bounds__(256) void k_gemm1(const float* __restrict__ A,
                                               const float* __restrict__ W1,
                                               const float* __restrict__ b1) {
  extern __shared__ float sm[];
  float* sAT = sm;              // [128 k][132 e-padded]
  float* sB  = sm + 128 * 132;  // [128 k][128 c]
  int tid = threadIdx.x;
  int e0 = blockIdx.x * TB;

  for (int idx = tid; idx < 128 * 128; idx += 256) {
    int e = idx >> 7, k = idx & 127;
    sAT[k * 132 + e] = (e0 + e < NEDGE) ? A[(size_t)(e0 + e) * 128 + k] : 0.f;
    sB[idx] = W1[idx];
  }
  __syncthreads();

  int ty = tid >> 4, tx = tid & 15;
  int ea = ty * 4, ca = tx * 4;
  float C[8][8];
#pragma unroll
  for (int i = 0; i < 8; ++i)
#pragma unroll
    for (int j = 0; j < 8; ++j) C[i][j] = 0.f;

#pragma unroll 4
  for (int k = 0; k < 128; ++k) {
    float4 A0 = *(const float4*)&sAT[k * 132 + ea];
    float4 A1 = *(const float4*)&sAT[k * 132 + 64 + ea];
    float4 B0 = *(const float4*)&sB[k * 128 + ca];
    float4 B1 = *(const float4*)&sB[k * 128 + 64 + ca];
    float a[8] = {A0.x, A0.y, A0.z, A0.w, A1.x, A1.y, A1.z, A1.w};
    float b[8] = {B0.x, B0.y, B0.z, B0.w, B1.x, B1.y, B1.z, B1.w};
#pragma unroll
    for (int i = 0; i < 8; ++i)
#pragma unroll
      for (int j = 0; j < 8; ++j) C[i][j] = fmaf(a[i], b[j], C[i][j]);
  }
  __syncthreads();  // done reading sAT; reuse as transpose staging [c][e]

#pragma unroll
  for (int j = 0; j < 8; ++j) {
    int c = (j < 4) ? ca + j : 60 + ca + j;
    float bj = b1[c];
#pragma unroll
    for (int i = 0; i < 8; ++i) {
      int e = (i < 4) ? ea + i : 60 + ea + i;
      float v = C[i][j] + bj;
      sAT[c * 132 + e] = v > 0.f ? v : 0.f;
    }
  }
  __syncthreads();
  for (int idx = tid; idx < 128 * 128; idx += 256) {
    int c = idx >> 7, e = idx & 127;
    if (e0 + e < NEDGE) g_hT[(size_t)c * NEDGE + e0 + e] = sAT[c * 132 + e];
  }
}

// ---------------- K2: fused GEMM2 + tensor product + scatter ----------------
static constexpr int S_HT  = 0;               // 129*132
static constexpr int S_W   = 129 * 132;       // 129*128 (W2 chunk, reused as C-stage)
static constexpr int S_S   = S_W + 129 * 128; // 128*48 s_in
static constexpr int S_DOT = S_S + 128 * 48;  // 128*10
static constexpr int S_VIN = S_DOT + 128 * 10;// 128*30
static constexpr int S_SH  = S_VIN + 128 * 30;// 128*4
static constexpr int S_AC0 = S_SH + 128 * 4;  // 128*48
static constexpr int S_YA  = S_AC0 + 128 * 48;// 128*10
static constexpr int S_YB  = S_YA + 128 * 10; // 128*30
static constexpr int S_TOT = S_YB + 128 * 30; // 56580 floats
static constexpr int K2_SMEM = S_TOT * 4;     // 226320 B  (< 227 KB limit)

__global__ __launch_bounds__(256) void k_fused(const int* __restrict__ eidx,
                                               const float* __restrict__ node_attr,
                                               const float* __restrict__ edge_sh,
                                               const float* __restrict__ W2,
                                               const float* __restrict__ b2) {
  extern __shared__ float sm[];
  float* sHT  = sm + S_HT;
  float* sW   = sm + S_W;
  float* sS   = sm + S_S;
  float* sDot = sm + S_DOT;
  float* sVin = sm + S_VIN;
  float* sSh  = sm + S_SH;
  float* sAc0 = sm + S_AC0;
  float* sYa  = sm + S_YA;
  float* sYb  = sm + S_YB;

  int tid = threadIdx.x;
  int e0 = blockIdx.x * TB;

  // load h^T tile (row 128 = 1.0 for bias folding)
  for (int idx = tid; idx < 128 * 128; idx += 256) {
    int k = idx >> 7, e = idx & 127;
    sHT[k * 132 + e] = (e0 + e < NEDGE) ? g_hT[(size_t)k * NEDGE + e0 + e] : 0.f;
  }
  if (tid < 128) sHT[128 * 132 + tid] = 1.0f;

  // zero accumulators (sAc0, sYa, sYb are contiguous)
  for (int idx = tid; idx < 128 * (48 + 10 + 30); idx += 256) sAc0[idx] = 0.f;

  // left vectors
  {
    int e = tid >> 1, half = tid & 1;
    int eg = e0 + e;
    if (eg < NEDGE) {
      int dst = eidx[NEDGE + eg];
      const float* x = node_attr + (size_t)dst * 78;
      for (int u = half * 24; u < half * 24 + 24; ++u) sS[e * 48 + u] = x[u];
      for (int m = half * 15; m < half * 15 + 15; ++m) sVin[e * 30 + m] = x[48 + m];
      if (!half)
        for (int i = 0; i < 4; ++i) sSh[e * 4 + i] = edge_sh[(size_t)eg * 4 + i];
    }
  }
  __syncthreads();
  {
    int e = tid >> 1, half = tid & 1;
    float s1 = sSh[e * 4 + 1], s2 = sSh[e * 4 + 2], s3 = sSh[e * 4 + 3];
    for (int u = half * 5; u < half * 5 + 5; ++u)
      sDot[e * 10 + u] = (sVin[e * 30 + u * 3] * s1 + sVin[e * 30 + u * 3 + 1] * s2 +
                          sVin[e * 30 + u * 3 + 2] * s3) * INV_SQRT3;
  }

  int ty = tid >> 4, tx = tid & 15;
  int ea = ty * 4, ca = tx * 4;
  int e_ = tid >> 1, half_ = tid & 1;

  // chunk schedule: 4x w2(120) -> [scale sS by sh0] -> 18x w1(128) -> 4x w4(120) -> 1x w3(100)
  for (int ci = 0; ci < 27; ++ci) {
    int type, jstart, cnt, rel;
    if (ci < 4)       { type = 2; rel = ci * 120;        jstart = OFF2 + rel; cnt = 120; }
    else if (ci < 22) { type = 1; rel = (ci - 4) * 128;  jstart = rel;        cnt = 128; }
    else if (ci < 26) { type = 4; rel = (ci - 22) * 120; jstart = OFF4 + rel; cnt = 120; }
    else              { type = 3; rel = 0;               jstart = OFF3;       cnt = 100; }

    __syncthreads();  // prev epilogue done with sW
    for (int idx = tid; idx < 129 * 128; idx += 256) {
      int k = idx >> 7, j = idx & 127;
      float v = 0.f;
      if (j < cnt) v = (k < 128) ? W2[(size_t)k * WTOT + jstart + j] : b2[jstart + j];
      sW[idx] = v;
    }
    __syncthreads();

    float C[8][8];
#pragma unroll
    for (int i = 0; i < 8; ++i)
#pragma unroll
      for (int j = 0; j < 8; ++j) C[i][j] = 0.f;

#pragma unroll 3
    for (int k = 0; k < 129; ++k) {
      float4 A0 = *(const float4*)&sHT[k * 132 + ea];
      float4 A1 = *(const float4*)&sHT[k * 132 + 64 + ea];
      float4 B0 = *(const float4*)&sW[k * 128 + ca];
      float4 B1 = *(const float4*)&sW[k * 128 + 64 + ca];
      float a[8] = {A0.x, A0.y, A0.z, A0.w, A1.x, A1.y, A1.z, A1.w};
      float b[8] = {B0.x, B0.y, B0.z, B0.w, B1.x, B1.y, B1.z, B1.w};
#pragma unroll
      for (int i = 0; i < 8; ++i)
#pragma unroll
        for (int j = 0; j < 8; ++j) C[i][j] = fmaf(a[i], b[j], C[i][j]);
    }
    __syncthreads();  // done reading sW as weights; reuse as C-stage [e][jj]

#pragma unroll
    for (int i = 0; i < 8; ++i) {
      int e = (i < 4) ? ea + i : 60 + ea + i;
      *(float4*)&sW[e * 128 + ca]      = make_float4(C[i][0], C[i][1], C[i][2], C[i][3]);
      *(float4*)&sW[e * 128 + 64 + ca] = make_float4(C[i][4], C[i][5], C[i][6], C[i][7]);
    }
    __syncthreads();

    // ownership-partitioned epilogue (2 threads per edge, no atomics)
    if (type == 1 || type == 4) {
      const float* mult = (type == 1) ? (sS + e_ * 48) : (sDot + e_ * 10);
      int umax = (type == 1) ? 47 : 9;
      const float* Cs = sW + e_ * 128 - rel;  // index with u*48+v (>= rel)
#pragma unroll 4
      for (int vv = 0; vv < 24; ++vv) {
        int v = half_ * 24 + vv;
        int d = rel - v;
        int u0 = d > 0 ? (d + 47) / 48 : 0;
        int u1 = (rel + cnt - 1 - v) / 48; if (u1 > umax) u1 = umax;
        float p = 0.f;
        for (int u = u0; u <= u1; ++u) p = fmaf(Cs[u * 48 + v], mult[u], p);
        sAc0[e_ * 48 + v] += p;
      }
    } else if (type == 2) {
      const float* Cs = sW + e_ * 128 - rel;
#pragma unroll
      for (int vv = 0; vv < 5; ++vv) {
        int v = half_ * 5 + vv;
        int d = rel - v;
        int u0 = d > 0 ? (d + 9) / 10 : 0;
        int u1 = (rel + cnt - 1 - v) / 10; if (u1 > 47) u1 = 47;
        float p = 0.f;
        for (int u = u0; u <= u1; ++u) p = fmaf(Cs[u * 10 + v], sS[e_ * 48 + u], p);
        sYa[e_ * 10 + v] += p;
      }
    } else {  // w3
      const float* Cs = sW + e_ * 128;
#pragma unroll
      for (int vv = 0; vv < 5; ++vv) {
        int v = half_ * 5 + vv;
        float y0 = 0.f, y1 = 0.f, y2 = 0.f;
#pragma unroll
        for (int u = 0; u < 10; ++u) {
          float wv = Cs[u * 10 + v];
          y0 = fmaf(wv, sVin[e_ * 30 + u * 3 + 0], y0);
          y1 = fmaf(wv, sVin[e_ * 30 + u * 3 + 1], y1);
          y2 = fmaf(wv, sVin[e_ * 30 + u * 3 + 2], y2);
        }
        sYb[e_ * 30 + v * 3 + 0] += y0;
        sYb[e_ * 30 + v * 3 + 1] += y1;
        sYb[e_ * 30 + v * 3 + 2] += y2;
      }
    }

    if (ci == 3) {  // w2 phase done -> scale s by sh0 for the w1 phase
      __syncthreads();
      float s0 = sSh[e_ * 4 + 0];
      for (int vv = 0; vv < 24; ++vv) sS[e_ * 48 + half_ * 24 + vv] *= s0;
    }
  }
  __syncthreads();

  // final per-edge output + scatter to node sums
  {
    int eg = e0 + e_;
    if (eg < NEDGE) {
      int src = eidx[eg];
      float s0 = sSh[e_ * 4], s1 = sSh[e_ * 4 + 1], s2 = sSh[e_ * 4 + 2], s3 = sSh[e_ * 4 + 3];
      float* dp = g_sum + (size_t)src * 78;
      for (int vv = 0; vv < 24; ++vv) {
        int v = half_ * 24 + vv;
        atomicAdd(&dp[v], sAc0[e_ * 48 + v] * NORM01);
      }
      for (int vv = 0; vv < 5; ++vv) {
        int v = half_ * 5 + vv;
        float ya = sYa[e_ * 10 + v];
        atomicAdd(&dp[48 + v * 3 + 0], (ya * s1 + sYb[e_ * 30 + v * 3 + 0] * s0) * NORM01);
        atomicAdd(&dp[48 + v * 3 + 1], (ya * s2 + sYb[e_ * 30 + v * 3 + 1] * s0) * NORM01);
        atomicAdd(&dp[48 + v * 3 + 2], (ya * s3 + sYb[e_ * 30 + v * 3 + 2] * s0) * NORM01);
      }
      if (!half_) atomicAdd(&g_cnt[src], 1.f);
    }
  }
}

// ---------------- K3: node finalize (mean + residual) + BN statistics ----------------
__global__ __launch_bounds__(256) void k_node(const float* __restrict__ node_attr,
                                              float* __restrict__ dout) {
  __shared__ float sP[106];
  int tid = threadIdx.x;
  if (tid < 106) sP[tid] = 0.f;
  __syncthreads();

  int n = blockIdx.x * blockDim.x + tid;
  bool valid = n < NNODE;
  float inv = 1.f;
  if (valid) inv = 1.f / fmaxf(g_cnt[n], 1.f);
  const float* srow  = g_sum + (valid ? (size_t)n * 78 : 0);
  const float* narow = node_attr + (valid ? (size_t)n * 78 : 0);

  for (int v = 0; v < 48; ++v) {
    float val = 0.f;
    if (valid) { val = srow[v] * inv + narow[v]; dout[(size_t)n * 78 + v] = val; }
    float s = val, q = val * val;
#pragma unroll
    for (int o = 16; o; o >>= 1) {
      s += __shfl_xor_sync(0xffffffffu, s, o);
      q += __shfl_xor_sync(0xffffffffu, q, o);
    }
    if ((tid & 31) == 0) { atomicAdd(&sP[v], s); atomicAdd(&sP[48 + v], q); }
  }
  for (int u = 0; u < 10; ++u) {
    float q = 0.f;
    for (int i = 0; i < 3; ++i) {
      float val = 0.f;
      int c = 48 + u * 3 + i;
      if (valid) { val = srow[c] * inv + narow[c]; dout[(size_t)n * 78 + c] = val; }
      q += val * val;
    }
#pragma unroll
    for (int o = 16; o; o >>= 1) q += __shfl_xor_sync(0xffffffffu, q, o);
    if ((tid & 31) == 0) atomicAdd(&sP[96 + u], q);
  }
  __syncthreads();
  if (tid < 106) atomicAdd(&g_stats[tid], sP[tid]);
}

// ---------------- K4: apply batch norm in place ----------------
__global__ void k_bn(const float* __restrict__ bnw, const float* __restrict__ bnb,
                     float* __restrict__ dout) {
  int idx = blockIdx.x * blockDim.x + threadIdx.x;
  if (idx >= NNODE * 78) return;
  int c = idx % 78;
  float x = dout[idx];
  if (c < 48) {
    float mean = g_stats[c] * (1.f / NNODE);
    float var  = g_stats[48 + c] * (1.f / NNODE) - mean * mean;
    dout[idx] = (x - mean) * rsqrtf(var + EPS_BN) * bnw[c] + bnb[c];
  } else {
    int u = (c - 48) / 3;
    float vn = g_stats[96 + u] * (1.f / (3.f * NNODE));
    dout[idx] = x * rsqrtf(vn + EPS_BN) * bnw[48 + u];
  }
}

// ---------------- launch ----------------
extern "C" void kernel_launch(void* const* d_in, const int* in_sizes, int n_in,
                              void* d_out, int out_size) {
  const float* node_attr  = (const float*)d_in[0];
  const int*   edge_index = (const int*)d_in[1];
  const float* edge_attr  = (const float*)d_in[2];
  const float* edge_sh    = (const float*)d_in[3];
  const float* fc_w1      = (const float*)d_in[4];
  const float* fc_b1      = (const float*)d_in[5];
  const float* fc_w2      = (const float*)d_in[6];
  const float* fc_b2      = (const float*)d_in[7];
  const float* bn_w       = (const float*)d_in[8];
  const float* bn_b       = (const float*)d_in[9];
  float* out = (float*)d_out;

  cudaFuncSetAttribute(k_gemm1, cudaFuncAttributeMaxDynamicSharedMemorySize, K1_SMEM);
  cudaFuncSetAttribute(k_fused, cudaFuncAttributeMaxDynamicSharedMemorySize, K2_SMEM);

  k_zero<<<256, 256>>>();
  k_gemm1<<<NBLK, 256, K1_SMEM>>>(edge_attr, fc_w1, fc_b1);
  k_fused<<<NBLK, 256, K2_SMEM>>>(edge_index, node_attr, edge_sh, fc_w2, fc_b2);
  k_node<<<(NNODE + 255) / 256, 256>>>(node_attr, out);
  k_bn<<<(NNODE * 78 + 255) / 256, 256>>>(bn_w, bn_b, out);
}

// round 2
// speedup vs baseline: 1.0006x; 1.0006x over previous
#include <cuda_runtime.h>

// ---------------- problem constants ----------------
static constexpr int NNODE = 10000;
static constexpr int NEDGE = 50000;
static constexpr int NSC   = 48;    // NS
static constexpr int NVC   = 10;    // NV
static constexpr int HID   = 128;
static constexpr int WTOT  = 3364;  // 2304 + 480 + 100 + 480
static constexpr int OFF2  = 2304;
static constexpr int OFF3  = 2784;
static constexpr int OFF4  = 2884;
static constexpr int TB    = 128;                      // edges per tile
static constexpr int NBLK  = (NEDGE + TB - 1) / TB;    // 391

#define EPS_BN     1e-5f
#define INV_SQRT3  0.57735026918962576f
#define NORM01     0.13130643285972254f   /* 1/sqrt(58) */

// ---------------- scratch (static device memory; no cudaMalloc) ----------------
__device__ float g_hT[(size_t)HID * NEDGE];   // h transposed [k][e], 25.6 MB
__device__ float g_sum[(size_t)NNODE * 78];   // per-node message sums
__device__ float g_cnt[NNODE];                // per-node edge counts
__device__ float g_stats[106];                // [0:48) sum_s, [48:96) sumsq_s, [96:106) sum v^2

// ---------------- K0: zero scratch ----------------
__global__ void k_zero() {
  int idx = blockIdx.x * blockDim.x + threadIdx.x;
  int stride = gridDim.x * blockDim.x;
  for (int i = idx; i < NNODE * 78; i += stride) g_sum[i] = 0.f;
  for (int i = idx; i < NNODE; i += stride) g_cnt[i] = 0.f;
  if (idx < 106) g_stats[idx] = 0.f;
}

// ---------------- K1: h = relu(edge_attr @ W1 + b1), stored transposed ----------------
static constexpr int K1_SMEM = (128 * 132 + 128 * 128) * 4;

__global__ __launch_bounds__(256) void k_gemm1(const float* __restrict__ A,
                                               const float* __restrict__ W1,
                                               const float* __restrict__ b1) {
  extern __shared__ float sm[];
  float* sAT = sm;              // [128 k][132 e-padded]
  float* sB  = sm + 128 * 132;  // [128 k][128 c]
  int tid = threadIdx.x;
  int e0 = blockIdx.x * TB;

  for (int idx = tid; idx < 128 * 128; idx += 256) {
    int e = idx >> 7, k = idx & 127;
    sAT[k * 132 + e] = (e0 + e < NEDGE) ? A[(size_t)(e0 + e) * 128 + k] : 0.f;
    sB[idx] = W1[idx];
  }
  __syncthreads();

  int ty = tid >> 4, tx = tid & 15;
  int ea = ty * 4, ca = tx * 4;
  float C[8][8];
#pragma unroll
  for (int i = 0; i < 8; ++i)
#pragma unroll
    for (int j = 0; j < 8; ++j) C[i][j] = 0.f;

#pragma unroll 4
  for (int k = 0; k < 128; ++k) {
    float4 A0 = *(const float4*)&sAT[k * 132 + ea];
    float4 A1 = *(const float4*)&sAT[k * 132 + 64 + ea];
    float4 B0 = *(const float4*)&sB[k * 128 + ca];
    float4 B1 = *(const float4*)&sB[k * 128 + 64 + ca];
    float a[8] = {A0.x, A0.y, A0.z, A0.w, A1.x, A1.y, A1.z, A1.w};
    float b[8] = {B0.x, B0.y, B0.z, B0.w, B1.x, B1.y, B1.z, B1.w};
#pragma unroll
    for (int i = 0; i < 8; ++i)
#pragma unroll
      for (int j = 0; j < 8; ++j) C[i][j] = fmaf(a[i], b[j], C[i][j]);
  }
  __syncthreads();  // done reading sAT; reuse as transpose staging [c][e]

#pragma unroll
  for (int j = 0; j < 8; ++j) {
    int c = (j < 4) ? ca + j : 60 + ca + j;
    float bj = b1[c];
#pragma unroll
    for (int i = 0; i < 8; ++i) {
      int e = (i < 4) ? ea + i : 60 + ea + i;
      float v = C[i][j] + bj;
      sAT[c * 132 + e] = v > 0.f ? v : 0.f;
    }
  }
  __syncthreads();
  for (int idx = tid; idx < 128 * 128; idx += 256) {
    int c = idx >> 7, e = idx & 127;
    if (e0 + e < NEDGE) g_hT[(size_t)c * NEDGE + e0 + e] = sAT[c * 132 + e];
  }
}

// ---------------- K2: fused GEMM2 + tensor product + scatter ----------------
static constexpr int S_HT  = 0;               // 129*132
static constexpr int S_W   = 129 * 132;       // 129*128 (W2 chunk, reused as C-stage)
static constexpr int S_S   = S_W + 129 * 128; // 128*48 s_in
static constexpr int S_DOT = S_S + 128 * 48;  // 128*10
static constexpr int S_VIN = S_DOT + 128 * 10;// 128*30
static constexpr int S_SH  = S_VIN + 128 * 30;// 128*4
static constexpr int S_AC0 = S_SH + 128 * 4;  // 128*48
static constexpr int S_YA  = S_AC0 + 128 * 48;// 128*10
static constexpr int S_YB  = S_YA + 128 * 10; // 128*30
static constexpr int S_TOT = S_YB + 128 * 30; // 56580 floats
static constexpr int K2_SMEM = S_TOT * 4;     // 226320 B  (< 227 KB limit)

__global__ __launch_bounds__(256) void k_fused(const int* __restrict__ eidx,
                                               const float* __restrict__ node_attr,
                                               const float* __restrict__ edge_sh,
                                               const float* __restrict__ W2,
                                               const float* __restrict__ b2) {
  extern __shared__ float sm[];
  float* sHT  = sm + S_HT;
  float* sW   = sm + S_W;
  float* sS   = sm + S_S;
  float* sDot = sm + S_DOT;
  float* sVin = sm + S_VIN;
  float* sSh  = sm + S_SH;
  float* sAc0 = sm + S_AC0;
  float* sYa  = sm + S_YA;
  float* sYb  = sm + S_YB;

  int tid = threadIdx.x;
  int e0 = blockIdx.x * TB;

  // load h^T tile (row 128 = 1.0 for bias folding)
  for (int idx = tid; idx < 128 * 128; idx += 256) {
    int k = idx >> 7, e = idx & 127;
    sHT[k * 132 + e] = (e0 + e < NEDGE) ? g_hT[(size_t)k * NEDGE + e0 + e] : 0.f;
  }
  if (tid < 128) sHT[128 * 132 + tid] = 1.0f;

  // zero accumulators (sAc0, sYa, sYb are contiguous)
  for (int idx = tid; idx < 128 * (48 + 10 + 30); idx += 256) sAc0[idx] = 0.f;

  // left vectors
  {
    int e = tid >> 1, half = tid & 1;
    int eg = e0 + e;
    if (eg < NEDGE) {
      int dst = eidx[NEDGE + eg];
      const float* x = node_attr + (size_t)dst * 78;
      for (int u = half * 24; u < half * 24 + 24; ++u) sS[e * 48 + u] = x[u];
      for (int m = half * 15; m < half * 15 + 15; ++m) sVin[e * 30 + m] = x[48 + m];
      if (!half)
        for (int i = 0; i < 4; ++i) sSh[e * 4 + i] = edge_sh[(size_t)eg * 4 + i];
    }
  }
  __syncthreads();
  {
    int e = tid >> 1, half = tid & 1;
    float s1 = sSh[e * 4 + 1], s2 = sSh[e * 4 + 2], s3 = sSh[e * 4 + 3];
    for (int u = half * 5; u < half * 5 + 5; ++u)
      sDot[e * 10 + u] = (sVin[e * 30 + u * 3] * s1 + sVin[e * 30 + u * 3 + 1] * s2 +
                          sVin[e * 30 + u * 3 + 2] * s3) * INV_SQRT3;
  }

  int ty = tid >> 4, tx = tid & 15;
  int ea = ty * 4, ca = tx * 4;
  int e_ = tid >> 1, half_ = tid & 1;

  // chunk schedule: 4x w2(120) -> [scale sS by sh0] -> 18x w1(128) -> 4x w4(120) -> 1x w3(100)
  for (int ci = 0; ci < 27; ++ci) {
    int type, jstart, cnt, rel;
    if (ci < 4)       { type = 2; rel = ci * 120;        jstart = OFF2 + rel; cnt = 120; }
    else if (ci < 22) { type = 1; rel = (ci - 4) * 128;  jstart = rel;        cnt = 128; }
    else if (ci < 26) { type = 4; rel = (ci - 22) * 120; jstart = OFF4 + rel; cnt = 120; }
    else              { type = 3; rel = 0;               jstart = OFF3;       cnt = 100; }

    __syncthreads();  // prev epilogue done with sW
    for (int idx = tid; idx < 129 * 128; idx += 256) {
      int k = idx >> 7, j = idx & 127;
      float v = 0.f;
      if (j < cnt) v = (k < 128) ? W2[(size_t)k * WTOT + jstart + j] : b2[jstart + j];
      sW[idx] = v;
    }
    __syncthreads();

    float C[8][8];
#pragma unroll
    for (int i = 0; i < 8; ++i)
#pragma unroll
      for (int j = 0; j < 8; ++j) C[i][j] = 0.f;

#pragma unroll 3
    for (int k = 0; k < 129; ++k) {
      float4 A0 = *(const float4*)&sHT[k * 132 + ea];
      float4 A1 = *(const float4*)&sHT[k * 132 + 64 + ea];
      float4 B0 = *(const float4*)&sW[k * 128 + ca];
      float4 B1 = *(const float4*)&sW[k * 128 + 64 + ca];
      float a[8] = {A0.x, A0.y, A0.z, A0.w, A1.x, A1.y, A1.z, A1.w};
      float b[8] = {B0.x, B0.y, B0.z, B0.w, B1.x, B1.y, B1.z, B1.w};
#pragma unroll
      for (int i = 0; i < 8; ++i)
#pragma unroll
        for (int j = 0; j < 8; ++j) C[i][j] = fmaf(a[i], b[j], C[i][j]);
    }
    __syncthreads();  // done reading sW as weights; reuse as C-stage [e][jj]

#pragma unroll
    for (int i = 0; i < 8; ++i) {
      int e = (i < 4) ? ea + i : 60 + ea + i;
      *(float4*)&sW[e * 128 + ca]      = make_float4(C[i][0], C[i][1], C[i][2], C[i][3]);
      *(float4*)&sW[e * 128 + 64 + ca] = make_float4(C[i][4], C[i][5], C[i][6], C[i][7]);
    }
    __syncthreads();

    // ownership-partitioned epilogue (2 threads per edge, no atomics)
    if (type == 1 || type == 4) {
      const float* mult = (type == 1) ? (sS + e_ * 48) : (sDot + e_ * 10);
      int umax = (type == 1) ? 47 : 9;
      const float* Cs = sW + e_ * 128 - rel;  // index with u*48+v (>= rel)
#pragma unroll 4
      for (int vv = 0; vv < 24; ++vv) {
        int v = half_ * 24 + vv;
        int d = rel - v;
        int u0 = d > 0 ? (d + 47) / 48 : 0;
        int u1 = (rel + cnt - 1 - v) / 48; if (u1 > umax) u1 = umax;
        float p = 0.f;
        for (int u = u0; u <= u1; ++u) p = fmaf(Cs[u * 48 + v], mult[u], p);
        sAc0[e_ * 48 + v] += p;
      }
    } else if (type == 2) {
      const float* Cs = sW + e_ * 128 - rel;
#pragma unroll
      for (int vv = 0; vv < 5; ++vv) {
        int v = half_ * 5 + vv;
        int d = rel - v;
        int u0 = d > 0 ? (d + 9) / 10 : 0;
        int u1 = (rel + cnt - 1 - v) / 10; if (u1 > 47) u1 = 47;
        float p = 0.f;
        for (int u = u0; u <= u1; ++u) p = fmaf(Cs[u * 10 + v], sS[e_ * 48 + u], p);
        sYa[e_ * 10 + v] += p;
      }
    } else {  // w3
      const float* Cs = sW + e_ * 128;
#pragma unroll
      for (int vv = 0; vv < 5; ++vv) {
        int v = half_ * 5 + vv;
        float y0 = 0.f, y1 = 0.f, y2 = 0.f;
#pragma unroll
        for (int u = 0; u < 10; ++u) {
          float wv = Cs[u * 10 + v];
          y0 = fmaf(wv, sVin[e_ * 30 + u * 3 + 0], y0);
          y1 = fmaf(wv, sVin[e_ * 30 + u * 3 + 1], y1);
          y2 = fmaf(wv, sVin[e_ * 30 + u * 3 + 2], y2);
        }
        sYb[e_ * 30 + v * 3 + 0] += y0;
        sYb[e_ * 30 + v * 3 + 1] += y1;
        sYb[e_ * 30 + v * 3 + 2] += y2;
      }
    }

    if (ci == 3) {  // w2 phase done -> scale s by sh0 for the w1 phase
      __syncthreads();
      float s0 = sSh[e_ * 4 + 0];
      for (int vv = 0; vv < 24; ++vv) sS[e_ * 48 + half_ * 24 + vv] *= s0;
    }
  }
  __syncthreads();

  // final per-edge output + scatter to node sums
  {
    int eg = e0 + e_;
    if (eg < NEDGE) {
      int src = eidx[eg];
      float s0 = sSh[e_ * 4], s1 = sSh[e_ * 4 + 1], s2 = sSh[e_ * 4 + 2], s3 = sSh[e_ * 4 + 3];
      float* dp = g_sum + (size_t)src * 78;
      for (int vv = 0; vv < 24; ++vv) {
        int v = half_ * 24 + vv;
        atomicAdd(&dp[v], sAc0[e_ * 48 + v] * NORM01);
      }
      for (int vv = 0; vv < 5; ++vv) {
        int v = half_ * 5 + vv;
        float ya = sYa[e_ * 10 + v];
        atomicAdd(&dp[48 + v * 3 + 0], (ya * s1 + sYb[e_ * 30 + v * 3 + 0] * s0) * NORM01);
        atomicAdd(&dp[48 + v * 3 + 1], (ya * s2 + sYb[e_ * 30 + v * 3 + 1] * s0) * NORM01);
        atomicAdd(&dp[48 + v * 3 + 2], (ya * s3 + sYb[e_ * 30 + v * 3 + 2] * s0) * NORM01);
      }
      if (!half_) atomicAdd(&g_cnt[src], 1.f);
    }
  }
}

// ---------------- K3: node finalize (mean + residual) + BN statistics ----------------
__global__ __launch_bounds__(256) void k_node(const float* __restrict__ node_attr,
                                              float* __restrict__ dout) {
  __shared__ float sP[106];
  int tid = threadIdx.x;
  if (tid < 106) sP[tid] = 0.f;
  __syncthreads();

  int n = blockIdx.x * blockDim.x + tid;
  bool valid = n < NNODE;
  float inv = 1.f;
  if (valid) inv = 1.f / fmaxf(g_cnt[n], 1.f);
  const float* srow  = g_sum + (valid ? (size_t)n * 78 : 0);
  const float* narow = node_attr + (valid ? (size_t)n * 78 : 0);

  for (int v = 0; v < 48; ++v) {
    float val = 0.f;
    if (valid) { val = srow[v] * inv + narow[v]; dout[(size_t)n * 78 + v] = val; }
    float s = val, q = val * val;
#pragma unroll
    for (int o = 16; o; o >>= 1) {
      s += __shfl_xor_sync(0xffffffffu, s, o);
      q += __shfl_xor_sync(0xffffffffu, q, o);
    }
    if ((tid & 31) == 0) { atomicAdd(&sP[v], s); atomicAdd(&sP[48 + v], q); }
  }
  for (int u = 0; u < 10; ++u) {
    float q = 0.f;
    for (int i = 0; i < 3; ++i) {
      float val = 0.f;
      int c = 48 + u * 3 + i;
      if (valid) { val = srow[c] * inv + narow[c]; dout[(size_t)n * 78 + c] = val; }
      q += val * val;
    }
#pragma unroll
    for (int o = 16; o; o >>= 1) q += __shfl_xor_sync(0xffffffffu, q, o);
    if ((tid & 31) == 0) atomicAdd(&sP[96 + u], q);
  }
  __syncthreads();
  if (tid < 106) atomicAdd(&g_stats[tid], sP[tid]);
}

// ---------------- K4: apply batch norm in place ----------------
__global__ void k_bn(const float* __restrict__ bnw, const float* __restrict__ bnb,
                     float* __restrict__ dout) {
  int idx = blockIdx.x * blockDim.x + threadIdx.x;
  if (idx >= NNODE * 78) return;
  int c = idx % 78;
  float x = dout[idx];
  if (c < 48) {
    float mean = g_stats[c] * (1.f / NNODE);
    float var  = g_stats[48 + c] * (1.f / NNODE) - mean * mean;
    dout[idx] = (x - mean) * rsqrtf(var + EPS_BN) * bnw[c] + bnb[c];
  } else {
    int u = (c - 48) / 3;
    float vn = g_stats[96 + u] * (1.f / (3.f * NNODE));
    dout[idx] = x * rsqrtf(vn + EPS_BN) * bnw[48 + u];
  }
}

// ---------------- launch ----------------
extern "C" void kernel_launch(void* const* d_in, const int* in_sizes, int n_in,
                              void* d_out, int out_size) {
  const float* node_attr  = (const float*)d_in[0];
  const int*   edge_index = (const int*)d_in[1];
  const float* edge_attr  = (const float*)d_in[2];
  const float* edge_sh    = (const float*)d_in[3];
  const float* fc_w1      = (const float*)d_in[4];
  const float* fc_b1      = (const float*)d_in[5];
  const float* fc_w2      = (const float*)d_in[6];
  const float* fc_b2      = (const float*)d_in[7];
  const float* bn_w       = (const float*)d_in[8];
  const float* bn_b       = (const float*)d_in[9];
  float* out = (float*)d_out;

  cudaFuncSetAttribute(k_gemm1, cudaFuncAttributeMaxDynamicSharedMemorySize, K1_SMEM);
  cudaFuncSetAttribute(k_fused, cudaFuncAttributeMaxDynamicSharedMemorySize, K2_SMEM);

  k_zero<<<256, 256>>>();
  k_gemm1<<<NBLK, 256, K1_SMEM>>>(edge_attr, fc_w1, fc_b1);
  k_fused<<<NBLK, 256, K2_SMEM>>>(edge_index, node_attr, edge_sh, fc_w2, fc_b2);
  k_node<<<(NNODE + 255) / 256, 256>>>(node_attr, out);
  k_bn<<<(NNODE * 78 + 255) / 256, 256>>>(bn_w, bn_b, out);
}